// round 16
// baseline (speedup 1.0000x reference)
#include <cuda_runtime.h>
#include <cuda_bf16.h>
#include <math.h>
#include <stdint.h>

// Problem constants
#define BB 2
#define CC 128
#define GG 4
#define CG 32
#define NS 4096
#define SPLIT 2
#define JSPAN (NS / SPLIT)          // 2048 keys per split
// 128^-0.5 * log2(e): fold into Q so softmax works in exp2 domain
#define QSCALE 0.12751744154339495f

// ---------------- scratch (device globals) ----------------------------------
__device__ __nv_bfloat16 g_qh[BB * CC * NS];    // Q * QSCALE, bf16, [b][c][n]
__device__ __nv_bfloat16 g_kh[BB * CC * NS];
__device__ __nv_bfloat16 g_vh[BB * CC * NS];
__device__ __nv_bfloat16 g_pob[SPLIT * BB * NS * CC]; // per-split normalized O, [sp][b][n][c]
__device__ float g_pm[SPLIT * BB * NS];         // partial row max (log2 domain)
__device__ float g_pl[SPLIT * BB * NS];         // partial row sum
__device__ float g_part[16][16][2];             // GN partials [group][slab][sum,ssq]
__device__ __nv_bfloat16 g_wb[4 * CC * CC];     // bf16 weights: q,k,v,p  [o][c]

// ---------------- asm helpers -------------------------------------------------
__device__ __forceinline__ float ex2(float x) {
    float r; asm("ex2.approx.ftz.f32 %0, %1;" : "=f"(r) : "f"(x)); return r;
}
__device__ __forceinline__ uint32_t pack_bf16(float lo, float hi) {
    uint32_t d;
    asm("cvt.rn.bf16x2.f32 %0, %1, %2;" : "=r"(d) : "f"(hi), "f"(lo));
    return d;
}
__device__ __forceinline__ void cp16(void* dst_smem, const void* src) {
    uint32_t d = (uint32_t)__cvta_generic_to_shared(dst_smem);
    asm volatile("cp.async.cg.shared.global [%0], [%1], 16;\n" :: "r"(d), "l"(src));
}
__device__ __forceinline__ void ldsm_x4(uint32_t* r, const void* p) {
    uint32_t a = (uint32_t)__cvta_generic_to_shared(p);
    asm volatile("ldmatrix.sync.aligned.m8n8.x4.shared.b16 {%0,%1,%2,%3}, [%4];"
        : "=r"(r[0]), "=r"(r[1]), "=r"(r[2]), "=r"(r[3]) : "r"(a));
}
__device__ __forceinline__ void ldsm_x4t(uint32_t* r, const void* p) {
    uint32_t a = (uint32_t)__cvta_generic_to_shared(p);
    asm volatile("ldmatrix.sync.aligned.m8n8.x4.trans.shared.b16 {%0,%1,%2,%3}, [%4];"
        : "=r"(r[0]), "=r"(r[1]), "=r"(r[2]), "=r"(r[3]) : "r"(a));
}
__device__ __forceinline__ void mma16816(float* d, const uint32_t* a, const uint32_t* b) {
    asm volatile(
        "mma.sync.aligned.m16n8k16.row.col.f32.bf16.bf16.f32 "
        "{%0,%1,%2,%3},{%4,%5,%6,%7},{%8,%9},{%0,%1,%2,%3};"
        : "+f"(d[0]), "+f"(d[1]), "+f"(d[2]), "+f"(d[3])
        : "r"(a[0]), "r"(a[1]), "r"(a[2]), "r"(a[3]), "r"(b[0]), "r"(b[1]));
}

// ---------------- prep: GN partial stats + weight bf16 conversion --------------
__global__ void __launch_bounds__(256) prep_kernel(
    const float* __restrict__ x, const float* __restrict__ c,
    const float* __restrict__ wq, const float* __restrict__ wk,
    const float* __restrict__ wv, const float* __restrict__ wp)
{
    int blk = blockIdx.x;
    if (blk >= 256) {
        int blk2 = blk - 256;                 // 0..63
        const float* ws[4] = { wq, wk, wv, wp };
        #pragma unroll
        for (int it = 0; it < 2; it++) {
            int p = blk2 * 512 + it * 256 + (int)threadIdx.x;
            int w_id = p >> 13, off = p & 8191;
            float2 w2 = *(const float2*)&ws[w_id][off * 2];
            ((uint32_t*)g_wb)[p] = pack_bf16(w2.x, w2.y);
        }
        return;
    }
    int slab = blk & 15;
    int gi   = blk >> 4;
    int which = gi >> 3, b = (gi >> 2) & 1, g = gi & 3;
    const float* in = which ? c : x;
    const float4* p4 = (const float4*)(in + ((size_t)(b * CC + g * CG)) * NS) +
                       (size_t)slab * 2048;

    float s = 0.f, ss = 0.f;
    #pragma unroll 4
    for (int i = threadIdx.x; i < 2048; i += 256) {
        float4 v = p4[i];
        s  += v.x + v.y + v.z + v.w;
        ss += v.x * v.x + v.y * v.y + v.z * v.z + v.w * v.w;
    }
    __shared__ float sh[16];
    #pragma unroll
    for (int o = 16; o; o >>= 1) {
        s  += __shfl_xor_sync(0xffffffffu, s, o);
        ss += __shfl_xor_sync(0xffffffffu, ss, o);
    }
    int w = threadIdx.x >> 5;
    if ((threadIdx.x & 31) == 0) { sh[w] = s; sh[8 + w] = ss; }
    __syncthreads();
    if (threadIdx.x == 0) {
        float ts = 0.f, tss = 0.f;
        #pragma unroll
        for (int i = 0; i < 8; i++) { ts += sh[i]; tss += sh[8 + i]; }
        g_part[gi][slab][0] = ts;
        g_part[gi][slab][1] = tss;
    }
}

// ---------------- fused GN-apply + QKV projection (bf16 mma, 3-way z) ---------
#define LDWB 136
#define LDRF 68
#define LDIB 72
__global__ void __launch_bounds__(256) qkv_kernel(
    const float* __restrict__ bq, const float* __restrict__ bk,
    const float* __restrict__ bv,
    const float* __restrict__ g1, const float* __restrict__ b1,
    const float* __restrict__ g2, const float* __restrict__ b2,
    const float* __restrict__ x,  const float* __restrict__ cin)
{
    extern __shared__ char smraw[];
    __nv_bfloat16* Wb  = (__nv_bfloat16*)smraw;               // [128][LDWB]
    float*         Raw = (float*)(Wb + CC * LDWB);            // [128][LDRF]
    __nv_bfloat16* In  = (__nv_bfloat16*)(Raw + CC * LDRF);   // [128][LDIB]
    float* SGA = (float*)(In + CC * LDIB);
    float* SGB = SGA + CC;

    int z = blockIdx.z;
    int b = blockIdx.y;
    int n0 = blockIdx.x * 64;
    int which = (z == 0) ? 1 : 0;
    const float* in    = which ? cin : x;
    const float* gamma = which ? g2 : g1;
    const float* beta  = which ? b2 : b1;
    const __nv_bfloat16* wsrc = g_wb + (size_t)z * CC * CC;
    const float* bias  = (z == 0) ? bq : (z == 1 ? bk : bv);
    __nv_bfloat16* out = (z == 0) ? g_qh : (z == 1 ? g_kh : g_vh);

    int tid = threadIdx.x;

    for (int idx = tid; idx < 2048; idx += 256) {
        int o = idx >> 4, ch = idx & 15;
        cp16(&Wb[o * LDWB + ch * 8], wsrc + o * CC + ch * 8);
    }
    for (int idx = tid; idx < 2048; idx += 256) {
        int c = idx >> 4, ch = idx & 15;
        cp16(&Raw[c * LDRF + ch * 4], &in[((size_t)b * CC + c) * NS + n0 + ch * 4]);
    }
    asm volatile("cp.async.commit_group;");

    if (tid < CC) {
        int chn = tid, g = chn >> 5;
        int gi = which * 8 + b * 4 + g;
        float s = 0.f, ss = 0.f;
        #pragma unroll
        for (int k = 0; k < 16; k++) { s += g_part[gi][k][0]; ss += g_part[gi][k][1]; }
        const float invM = 1.0f / (float)(CG * NS);
        float mean = s * invM;
        float var  = ss * invM - mean * mean;
        float rinv = rsqrtf(var + 1e-6f);
        float ga = gamma[chn] * rinv;
        SGA[chn] = ga;
        SGB[chn] = beta[chn] - mean * ga;
    }
    asm volatile("cp.async.wait_group 0;");
    __syncthreads();

    for (int idx = tid; idx < 2048; idx += 256) {
        int c = idx >> 4, q = idx & 15;
        float ga = SGA[c], be = SGB[c];
        float4 v = *(const float4*)&Raw[c * LDRF + q * 4];
        uint32_t* dst = (uint32_t*)&In[c * LDIB + q * 4];
        dst[0] = pack_bf16(v.x * ga + be, v.y * ga + be);
        dst[1] = pack_bf16(v.z * ga + be, v.w * ga + be);
    }
    __syncthreads();

    int lane = tid & 31, warp = tid >> 5;
    int m0 = warp * 16;
    const int rowK = (lane & 7) + ((lane & 8) ? 8 : 0);
    const int colK = ((lane & 16) ? 8 : 0);
    int orow = m0 + (lane >> 2);
    int ncol = (lane & 3) * 2;

    float acc[8][4];
    #pragma unroll
    for (int nf = 0; nf < 8; nf++)
        #pragma unroll
        for (int e = 0; e < 4; e++) acc[nf][e] = 0.f;

    #pragma unroll
    for (int kb = 0; kb < 8; kb++) {
        uint32_t aw[4];
        ldsm_x4(aw, &Wb[(m0 + rowK) * LDWB + kb * 16 + colK]);
        #pragma unroll
        for (int nb = 0; nb < 4; nb++) {
            uint32_t bf[4];
            ldsm_x4t(bf, &In[(kb * 16 + rowK) * LDIB + nb * 16 + colK]);
            mma16816(acc[2 * nb],     aw, bf);
            mma16816(acc[2 * nb + 1], aw, bf + 2);
        }
    }

    float sc = (z == 0) ? QSCALE : 1.0f;
    float bv0 = bias[orow], bv1 = bias[orow + 8];
    size_t ob0 = ((size_t)b * CC + orow) * NS + n0;
    size_t ob1 = ob0 + (size_t)8 * NS;
    #pragma unroll
    for (int nf = 0; nf < 8; nf++) {
        int n = nf * 8 + ncol;
        *(uint32_t*)&out[ob0 + n] =
            pack_bf16((acc[nf][0] + bv0) * sc, (acc[nf][1] + bv0) * sc);
        *(uint32_t*)&out[ob1 + n] =
            pack_bf16((acc[nf][2] + bv1) * sc, (acc[nf][3] + bv1) * sc);
    }
}

// ---------------- flash attention (bf16 mma, split-KV, BM=128) ----------------
// grid (NS/128, BB, SPLIT) = 128 CTAs, 256 threads = 8 warps (16 rows each).
// ROUND-6 SCHEDULE (frozen): K double-buffered w/ top-of-loop wait, V single-
// buffered w/ post-AV prefetch. K/V tiles now serve 8 warps -> K/V L2 traffic
// and cp.async smem writes HALVE. Per-warp register state identical to BM=64.
#define LDB 72
#define LDQ 136
#define SM_K (128 * LDB)

__global__ void __launch_bounds__(256, 1) attn_kernel()
{
    extern __shared__ __nv_bfloat16 sh[];
    __nv_bfloat16* Qs = sh;                                   // [128c][LDQ]
    __nv_bfloat16* Ksb[2] = { sh + 128 * LDQ, sh + 128 * LDQ + SM_K };
    __nv_bfloat16* Vs = sh + 128 * LDQ + 2 * SM_K;            // single buffer

    int b  = blockIdx.y;
    int sp = blockIdx.z;
    int i0 = blockIdx.x * 128;
    int tid = threadIdx.x, lane = tid & 31, warp = tid >> 5;
    int t = lane & 3;
    int m0 = warp * 16;   // 0..112

    const __nv_bfloat16* gq = g_qh + (size_t)b * CC * NS + i0;
    const __nv_bfloat16* gk = g_kh + (size_t)b * CC * NS + sp * JSPAN;
    const __nv_bfloat16* gv = g_vh + (size_t)b * CC * NS + sp * JSPAN;

    // prologue: Q (128x128), K0, V0
    for (int idx = tid; idx < 2048; idx += 256) {
        int c = idx >> 4, t8 = (idx & 15) * 8;
        cp16(&Qs[c * LDQ + t8], gq + (size_t)c * NS + t8);
    }
    for (int idx = tid; idx < 1024; idx += 256) {
        int c = idx >> 3, j8 = (idx & 7) * 8;
        cp16(&Ksb[0][c * LDB + j8], gk + (size_t)c * NS + j8);
        cp16(&Vs[c * LDB + j8], gv + (size_t)c * NS + j8);
    }
    asm volatile("cp.async.commit_group;");
    asm volatile("cp.async.wait_group 0;");
    __syncthreads();

    const int rowA = (lane & 7) + ((lane & 16) ? 8 : 0);
    const int colA = ((lane & 8) ? 8 : 0);
    const int rowK = (lane & 7) + ((lane & 8) ? 8 : 0);
    const int colK = ((lane & 16) ? 8 : 0);

    uint32_t qa[8][4];
    #pragma unroll
    for (int kb = 0; kb < 8; kb++)
        ldsm_x4t(qa[kb], &Qs[(kb * 16 + rowA) * LDQ + m0 + colA]);

    float mr0 = -1e30f, mr1 = -1e30f, lr0 = 0.f, lr1 = 0.f;
    float of[16][4];
    #pragma unroll
    for (int nt = 0; nt < 16; nt++)
        #pragma unroll
        for (int e = 0; e < 4; e++) of[nt][e] = 0.f;

    const int NT = JSPAN / 64;   // 32
    for (int jt = 0; jt < NT; jt++) {
        asm volatile("cp.async.wait_group 1;");
        __syncthreads();

        if (jt + 1 < NT) {
            int j0n = (jt + 1) * 64;
            __nv_bfloat16* kd = Ksb[(jt + 1) & 1];
            for (int idx = tid; idx < 1024; idx += 256) {
                int c = idx >> 3, j8 = (idx & 7) * 8;
                cp16(&kd[c * LDB + j8], gk + (size_t)c * NS + j0n + j8);
            }
        }
        asm volatile("cp.async.commit_group;");

        const __nv_bfloat16* Ks = Ksb[jt & 1];

        // ---- S = Q^T K ----
        float sf[8][4];
        #pragma unroll
        for (int nb = 0; nb < 8; nb++)
            #pragma unroll
            for (int e = 0; e < 4; e++) sf[nb][e] = 0.f;

        #pragma unroll
        for (int kb = 0; kb < 8; kb++) {
            #pragma unroll
            for (int nbp = 0; nbp < 4; nbp++) {
                uint32_t kf[4];
                ldsm_x4t(kf, &Ks[(kb * 16 + rowK) * LDB + nbp * 16 + colK]);
                mma16816(sf[2 * nbp],     qa[kb], kf);
                mma16816(sf[2 * nbp + 1], qa[kb], kf + 2);
            }
        }

        // ---- online softmax ----
        float mx0 = -1e30f, mx1 = -1e30f;
        #pragma unroll
        for (int nb = 0; nb < 8; nb++) {
            mx0 = fmaxf(mx0, fmaxf(sf[nb][0], sf[nb][1]));
            mx1 = fmaxf(mx1, fmaxf(sf[nb][2], sf[nb][3]));
        }
        mx0 = fmaxf(mx0, __shfl_xor_sync(0xffffffffu, mx0, 1));
        mx0 = fmaxf(mx0, __shfl_xor_sync(0xffffffffu, mx0, 2));
        mx1 = fmaxf(mx1, __shfl_xor_sync(0xffffffffu, mx1, 1));
        mx1 = fmaxf(mx1, __shfl_xor_sync(0xffffffffu, mx1, 2));

        float mn0 = fmaxf(mr0, mx0), mn1 = fmaxf(mr1, mx1);
        float cr0 = ex2(mr0 - mn0),  cr1 = ex2(mr1 - mn1);
        float rs0 = 0.f, rs1 = 0.f;
        #pragma unroll
        for (int nb = 0; nb < 8; nb++) {
            sf[nb][0] = ex2(sf[nb][0] - mn0);
            sf[nb][1] = ex2(sf[nb][1] - mn0);
            sf[nb][2] = ex2(sf[nb][2] - mn1);
            sf[nb][3] = ex2(sf[nb][3] - mn1);
            rs0 += sf[nb][0] + sf[nb][1];
            rs1 += sf[nb][2] + sf[nb][3];
        }
        rs0 += __shfl_xor_sync(0xffffffffu, rs0, 1);
        rs0 += __shfl_xor_sync(0xffffffffu, rs0, 2);
        rs1 += __shfl_xor_sync(0xffffffffu, rs1, 1);
        rs1 += __shfl_xor_sync(0xffffffffu, rs1, 2);
        lr0 = lr0 * cr0 + rs0;
        lr1 = lr1 * cr1 + rs1;
        mr0 = mn0; mr1 = mn1;

        #pragma unroll
        for (int nt = 0; nt < 16; nt++) {
            of[nt][0] *= cr0; of[nt][1] *= cr0;
            of[nt][2] *= cr1; of[nt][3] *= cr1;
        }

        uint32_t pa[4][4];
        #pragma unroll
        for (int kt = 0; kt < 4; kt++) {
            pa[kt][0] = pack_bf16(sf[2 * kt][0],     sf[2 * kt][1]);
            pa[kt][1] = pack_bf16(sf[2 * kt][2],     sf[2 * kt][3]);
            pa[kt][2] = pack_bf16(sf[2 * kt + 1][0], sf[2 * kt + 1][1]);
            pa[kt][3] = pack_bf16(sf[2 * kt + 1][2], sf[2 * kt + 1][3]);
        }

        asm volatile("cp.async.wait_group 1;");
        __syncthreads();

        // ---- O += P V^T ----
        #pragma unroll
        for (int ntp = 0; ntp < 8; ntp++) {
            #pragma unroll
            for (int kt = 0; kt < 4; kt++) {
                uint32_t vf[4];
                ldsm_x4(vf, &Vs[(ntp * 16 + rowA) * LDB + kt * 16 + colA]);
                mma16816(of[2 * ntp],     pa[kt], vf);
                mma16816(of[2 * ntp + 1], pa[kt], vf + 2);
            }
        }
        __syncthreads();

        if (jt + 1 < NT) {
            int j0n = (jt + 1) * 64;
            for (int idx = tid; idx < 1024; idx += 256) {
                int c = idx >> 3, j8 = (idx & 7) * 8;
                cp16(&Vs[c * LDB + j8], gv + (size_t)c * NS + j0n + j8);
            }
        }
        asm volatile("cp.async.commit_group;");
    }
    asm volatile("cp.async.wait_group 0;");

    // epilogue: per-split-normalized bf16 partials, [n][c] layout
    float inv0 = 1.0f / lr0, inv1 = 1.0f / lr1;
    int ig = i0 + m0 + (lane >> 2);
    __nv_bfloat16* po = g_pob + ((size_t)(sp * BB + b)) * NS * CC;
    #pragma unroll
    for (int nt = 0; nt < 16; nt++) {
        int c = 8 * nt + 2 * t;
        *(uint32_t*)&po[(size_t)ig * CC + c] =
            pack_bf16(of[nt][0] * inv0, of[nt][1] * inv0);
        *(uint32_t*)&po[(size_t)(ig + 8) * CC + c] =
            pack_bf16(of[nt][2] * inv1, of[nt][3] * inv1);
    }
    if (t == 0) {
        size_t mb = (size_t)(sp * BB + b) * NS;
        g_pm[mb + ig]     = mr0;
        g_pm[mb + ig + 8] = mr1;
        g_pl[mb + ig]     = lr0;
        g_pl[mb + ig + 8] = lr1;
    }
}

// ---------------- fused split-combine + output projection (bf16 mma) ----------
// grid (NS/32, BB, 2): 32-token tiles, 512 CTAs (round-13 form).
#define LDC 136
__global__ void __launch_bounds__(128) proj_out_kernel(
    const float* __restrict__ bias,
    const float* __restrict__ xres, float* __restrict__ out)
{
    extern __shared__ char smraw[];
    __nv_bfloat16* Wb = (__nv_bfloat16*)smraw;        // [64][LDC]
    __nv_bfloat16* P0 = Wb + 64 * LDC;                // [32 n][LDC c]
    __nv_bfloat16* P1 = P0 + 32 * LDC;                // [32 n][LDC c]
    __nv_bfloat16* In = P1 + 32 * LDC;                // [32 n][LDC c]
    float* A0 = (float*)(In + 32 * LDC);              // [32]
    float* A1 = A0 + 32;

    int b  = blockIdx.y;
    int mh = blockIdx.z;
    int n0 = blockIdx.x * 32;
    int tid = threadIdx.x;

    const __nv_bfloat16* wsrc = g_wb + 3 * CC * CC + (size_t)(mh * 64) * CC;
    const __nv_bfloat16* po0 = g_pob + (size_t)b * NS * CC + (size_t)n0 * CC;
    const __nv_bfloat16* po1 = g_pob + (size_t)(BB + b) * NS * CC + (size_t)n0 * CC;

    for (int idx = tid; idx < 512; idx += 128) {
        int r = idx >> 4, ch = (idx & 15) * 8;
        cp16(&P0[r * LDC + ch], po0 + r * CC + ch);
        cp16(&P1[r * LDC + ch], po1 + r * CC + ch);
    }
    for (int idx = tid; idx < 1024; idx += 128) {
        int r = idx >> 4, ch = (idx & 15) * 8;
        cp16(&Wb[r * LDC + ch], wsrc + r * CC + ch);
    }
    asm volatile("cp.async.commit_group;");

    if (tid < 32) {
        int i = n0 + tid;
        float m0v = g_pm[(size_t)b * NS + i];
        float m1v = g_pm[(size_t)(BB + b) * NS + i];
        float l0v = g_pl[(size_t)b * NS + i];
        float l1v = g_pl[(size_t)(BB + b) * NS + i];
        float mm = fmaxf(m0v, m1v);
        float e0 = l0v * ex2(m0v - mm), e1 = l1v * ex2(m1v - mm);
        float inv = 1.0f / (e0 + e1);
        A0[tid] = e0 * inv;
        A1[tid] = e1 * inv;
    }
    asm volatile("cp.async.wait_group 0;");
    __syncthreads();

    for (int idx = tid; idx < 32 * 64; idx += 128) {
        int n = idx >> 6, cp = idx & 63;
        uint32_t u0 = ((const uint32_t*)&P0[n * LDC])[cp];
        uint32_t u1 = ((const uint32_t*)&P1[n * LDC])[cp];
        __nv_bfloat162 h0 = *(__nv_bfloat162*)&u0;
        __nv_bfloat162 h1 = *(__nv_bfloat162*)&u1;
        float a0 = A0[n], a1 = A1[n];
        float rx = a0 * __bfloat162float(h0.x) + a1 * __bfloat162float(h1.x);
        float ry = a0 * __bfloat162float(h0.y) + a1 * __bfloat162float(h1.y);
        ((uint32_t*)&In[n * LDC])[cp] = pack_bf16(rx, ry);
    }
    __syncthreads();

    int lane = tid & 31, warp = tid >> 5;
    int m0 = warp * 16;
    const int rowA = (lane & 7) + ((lane & 16) ? 8 : 0);
    const int colA = ((lane & 8) ? 8 : 0);
    const int rowK = (lane & 7) + ((lane & 8) ? 8 : 0);
    const int colK = ((lane & 16) ? 8 : 0);

    float acc[4][4];
    #pragma unroll
    for (int nf = 0; nf < 4; nf++)
        #pragma unroll
        for (int e = 0; e < 4; e++) acc[nf][e] = 0.f;

    #pragma unroll
    for (int kb = 0; kb < 8; kb++) {
        uint32_t aw[4];
        ldsm_x4(aw, &Wb[(m0 + rowK) * LDC + kb * 16 + colK]);
        #pragma unroll
        for (int nb = 0; nb < 2; nb++) {
            uint32_t vf[4];
            ldsm_x4(vf, &In[(nb * 16 + rowA) * LDC + kb * 16 + colA]);
            mma16816(acc[2 * nb],     aw, vf);
            mma16816(acc[2 * nb + 1], aw, vf + 2);
        }
    }

    int orow = mh * 64 + m0 + (lane >> 2);
    int ncol = (lane & 3) * 2;
    float bv0 = bias[orow], bv1 = bias[orow + 8];
    size_t ob0 = ((size_t)b * CC + orow) * NS + n0;
    size_t ob1 = ob0 + (size_t)8 * NS;
    #pragma unroll
    for (int nf = 0; nf < 4; nf++) {
        int n = nf * 8 + ncol;
        float2 x0 = *(const float2*)&xres[ob0 + n];
        float2 x1 = *(const float2*)&xres[ob1 + n];
        float2 r0 = { acc[nf][0] + bv0 + x0.x, acc[nf][1] + bv0 + x0.y };
        float2 r1 = { acc[nf][2] + bv1 + x1.x, acc[nf][3] + bv1 + x1.y };
        *(float2*)&out[ob0 + n] = r0;
        *(float2*)&out[ob1 + n] = r1;
    }
}

// ---------------- launcher ---------------------------------------------------
extern "C" void kernel_launch(void* const* d_in, const int* in_sizes, int n_in,
                              void* d_out, int out_size)
{
    const float* x  = (const float*)d_in[0];
    const float* c  = (const float*)d_in[1];
    const float* g1 = (const float*)d_in[2];
    const float* b1 = (const float*)d_in[3];
    const float* g2 = (const float*)d_in[4];
    const float* b2 = (const float*)d_in[5];
    const float* wq = (const float*)d_in[6];
    const float* bq = (const float*)d_in[7];
    const float* wk = (const float*)d_in[8];
    const float* bk = (const float*)d_in[9];
    const float* wv = (const float*)d_in[10];
    const float* bv = (const float*)d_in[11];
    const float* wp = (const float*)d_in[12];
    const float* bp = (const float*)d_in[13];
    float* out = (float*)d_out;

    const int QKV_SMEM  = (CC * LDWB + CC * LDIB) * 2 + CC * LDRF * 4 + 2 * CC * 4;  // 89088
    const int PROJ_SMEM = (64 + 3 * 32) * LDC * 2 + 2 * 32 * 4;                      // 43776
    const int ATTN_SMEM = (128 * LDQ + 3 * SM_K) * 2;                                // 90112
    cudaFuncSetAttribute(qkv_kernel,      cudaFuncAttributeMaxDynamicSharedMemorySize, QKV_SMEM);
    cudaFuncSetAttribute(proj_out_kernel, cudaFuncAttributeMaxDynamicSharedMemorySize, PROJ_SMEM);
    cudaFuncSetAttribute(attn_kernel,     cudaFuncAttributeMaxDynamicSharedMemorySize, ATTN_SMEM);

    prep_kernel<<<320, 256>>>(x, c, wq, wk, wv, wp);

    dim3 gq(NS / 64, BB, 3);
    qkv_kernel<<<gq, 256, QKV_SMEM>>>(bq, bk, bv, g1, b1, g2, b2, x, c);

    dim3 ga(NS / 128, BB, SPLIT);
    attn_kernel<<<ga, 256, ATTN_SMEM>>>();

    dim3 gp(NS / 32, BB, 2);
    proj_out_kernel<<<gp, 128, PROJ_SMEM>>>(bp, x, out);
}

// round 17
// speedup vs baseline: 1.0260x; 1.0260x over previous
#include <cuda_runtime.h>
#include <cuda_bf16.h>
#include <math.h>
#include <stdint.h>

// Problem constants
#define BB 2
#define CC 128
#define GG 4
#define CG 32
#define NS 4096
#define SPLIT 2
#define JSPAN (NS / SPLIT)          // 2048 keys per split
// 128^-0.5 * log2(e): fold into Q so softmax works in exp2 domain
#define QSCALE 0.12751744154339495f

// ---------------- scratch (device globals) ----------------------------------
__device__ __nv_bfloat16 g_qh[BB * CC * NS];    // Q * QSCALE, bf16, [b][c][n]
__device__ __nv_bfloat16 g_kh[BB * CC * NS];
__device__ __nv_bfloat16 g_vh[BB * CC * NS];
__device__ __nv_bfloat16 g_pob[SPLIT * BB * NS * CC]; // per-split normalized O, [sp][b][n][c]
__device__ float g_pm[SPLIT * BB * NS];         // partial row max (log2 domain)
__device__ float g_pl[SPLIT * BB * NS];         // partial row sum
__device__ float g_part[16][16][2];             // GN partials [group][slab][sum,ssq]
__device__ __nv_bfloat16 g_wb[4 * CC * CC];     // bf16 weights: q,k,v,p  [o][c]

// ---------------- asm helpers -------------------------------------------------
__device__ __forceinline__ float ex2(float x) {
    float r; asm("ex2.approx.ftz.f32 %0, %1;" : "=f"(r) : "f"(x)); return r;
}
__device__ __forceinline__ uint32_t pack_bf16(float lo, float hi) {
    uint32_t d;
    asm("cvt.rn.bf16x2.f32 %0, %1, %2;" : "=r"(d) : "f"(hi), "f"(lo));
    return d;
}
__device__ __forceinline__ void cp16(void* dst_smem, const void* src) {
    uint32_t d = (uint32_t)__cvta_generic_to_shared(dst_smem);
    asm volatile("cp.async.cg.shared.global [%0], [%1], 16;\n" :: "r"(d), "l"(src));
}
__device__ __forceinline__ void ldsm_x4(uint32_t* r, const void* p) {
    uint32_t a = (uint32_t)__cvta_generic_to_shared(p);
    asm volatile("ldmatrix.sync.aligned.m8n8.x4.shared.b16 {%0,%1,%2,%3}, [%4];"
        : "=r"(r[0]), "=r"(r[1]), "=r"(r[2]), "=r"(r[3]) : "r"(a));
}
__device__ __forceinline__ void ldsm_x4t(uint32_t* r, const void* p) {
    uint32_t a = (uint32_t)__cvta_generic_to_shared(p);
    asm volatile("ldmatrix.sync.aligned.m8n8.x4.trans.shared.b16 {%0,%1,%2,%3}, [%4];"
        : "=r"(r[0]), "=r"(r[1]), "=r"(r[2]), "=r"(r[3]) : "r"(a));
}
__device__ __forceinline__ void mma16816(float* d, const uint32_t* a, const uint32_t* b) {
    asm volatile(
        "mma.sync.aligned.m16n8k16.row.col.f32.bf16.bf16.f32 "
        "{%0,%1,%2,%3},{%4,%5,%6,%7},{%8,%9},{%0,%1,%2,%3};"
        : "+f"(d[0]), "+f"(d[1]), "+f"(d[2]), "+f"(d[3])
        : "r"(a[0]), "r"(a[1]), "r"(a[2]), "r"(a[3]), "r"(b[0]), "r"(b[1]));
}

// ---------------- prep: GN partial stats + weight bf16 conversion --------------
// grid 320: blocks 0..255 = stats (gi = blk>>4, slab = blk&15, 16 slabs/group);
// blocks 256..319 = weight conversion.
__global__ void __launch_bounds__(256) prep_kernel(
    const float* __restrict__ x, const float* __restrict__ c,
    const float* __restrict__ wq, const float* __restrict__ wk,
    const float* __restrict__ wv, const float* __restrict__ wp)
{
    int blk = blockIdx.x;
    if (blk >= 256) {
        int blk2 = blk - 256;                 // 0..63
        const float* ws[4] = { wq, wk, wv, wp };
        #pragma unroll
        for (int it = 0; it < 2; it++) {
            int p = blk2 * 512 + it * 256 + (int)threadIdx.x;
            int w_id = p >> 13, off = p & 8191;
            float2 w2 = *(const float2*)&ws[w_id][off * 2];
            ((uint32_t*)g_wb)[p] = pack_bf16(w2.x, w2.y);
        }
        return;
    }
    int slab = blk & 15;
    int gi   = blk >> 4;
    int which = gi >> 3, b = (gi >> 2) & 1, g = gi & 3;
    const float* in = which ? c : x;
    const float4* p4 = (const float4*)(in + ((size_t)(b * CC + g * CG)) * NS) +
                       (size_t)slab * 2048;

    float s = 0.f, ss = 0.f;
    #pragma unroll 4
    for (int i = threadIdx.x; i < 2048; i += 256) {
        float4 v = p4[i];
        s  += v.x + v.y + v.z + v.w;
        ss += v.x * v.x + v.y * v.y + v.z * v.z + v.w * v.w;
    }
    __shared__ float sh[16];
    #pragma unroll
    for (int o = 16; o; o >>= 1) {
        s  += __shfl_xor_sync(0xffffffffu, s, o);
        ss += __shfl_xor_sync(0xffffffffu, ss, o);
    }
    int w = threadIdx.x >> 5;
    if ((threadIdx.x & 31) == 0) { sh[w] = s; sh[8 + w] = ss; }
    __syncthreads();
    if (threadIdx.x == 0) {
        float ts = 0.f, tss = 0.f;
        #pragma unroll
        for (int i = 0; i < 8; i++) { ts += sh[i]; tss += sh[8 + i]; }
        g_part[gi][slab][0] = ts;
        g_part[gi][slab][1] = tss;
    }
}

// ---------------- fused GN-apply + QKV projection (bf16 mma, 3-way z) ---------
#define LDWB 136
#define LDRF 68
#define LDIB 72
__global__ void __launch_bounds__(256) qkv_kernel(
    const float* __restrict__ bq, const float* __restrict__ bk,
    const float* __restrict__ bv,
    const float* __restrict__ g1, const float* __restrict__ b1,
    const float* __restrict__ g2, const float* __restrict__ b2,
    const float* __restrict__ x,  const float* __restrict__ cin)
{
    extern __shared__ char smraw[];
    __nv_bfloat16* Wb  = (__nv_bfloat16*)smraw;               // [128][LDWB]
    float*         Raw = (float*)(Wb + CC * LDWB);            // [128][LDRF]
    __nv_bfloat16* In  = (__nv_bfloat16*)(Raw + CC * LDRF);   // [128][LDIB]
    float* SGA = (float*)(In + CC * LDIB);
    float* SGB = SGA + CC;

    int z = blockIdx.z;
    int b = blockIdx.y;
    int n0 = blockIdx.x * 64;
    int which = (z == 0) ? 1 : 0;
    const float* in    = which ? cin : x;
    const float* gamma = which ? g2 : g1;
    const float* beta  = which ? b2 : b1;
    const __nv_bfloat16* wsrc = g_wb + (size_t)z * CC * CC;
    const float* bias  = (z == 0) ? bq : (z == 1 ? bk : bv);
    __nv_bfloat16* out = (z == 0) ? g_qh : (z == 1 ? g_kh : g_vh);

    int tid = threadIdx.x;

    for (int idx = tid; idx < 2048; idx += 256) {
        int o = idx >> 4, ch = idx & 15;
        cp16(&Wb[o * LDWB + ch * 8], wsrc + o * CC + ch * 8);
    }
    for (int idx = tid; idx < 2048; idx += 256) {
        int c = idx >> 4, ch = idx & 15;
        cp16(&Raw[c * LDRF + ch * 4], &in[((size_t)b * CC + c) * NS + n0 + ch * 4]);
    }
    asm volatile("cp.async.commit_group;");

    if (tid < CC) {
        int chn = tid, g = chn >> 5;
        int gi = which * 8 + b * 4 + g;
        float s = 0.f, ss = 0.f;
        #pragma unroll
        for (int k = 0; k < 16; k++) { s += g_part[gi][k][0]; ss += g_part[gi][k][1]; }
        const float invM = 1.0f / (float)(CG * NS);
        float mean = s * invM;
        float var  = ss * invM - mean * mean;
        float rinv = rsqrtf(var + 1e-6f);
        float ga = gamma[chn] * rinv;
        SGA[chn] = ga;
        SGB[chn] = beta[chn] - mean * ga;
    }
    asm volatile("cp.async.wait_group 0;");
    __syncthreads();

    for (int idx = tid; idx < 2048; idx += 256) {
        int c = idx >> 4, q = idx & 15;
        float ga = SGA[c], be = SGB[c];
        float4 v = *(const float4*)&Raw[c * LDRF + q * 4];
        uint32_t* dst = (uint32_t*)&In[c * LDIB + q * 4];
        dst[0] = pack_bf16(v.x * ga + be, v.y * ga + be);
        dst[1] = pack_bf16(v.z * ga + be, v.w * ga + be);
    }
    __syncthreads();

    int lane = tid & 31, warp = tid >> 5;
    int m0 = warp * 16;
    const int rowK = (lane & 7) + ((lane & 8) ? 8 : 0);
    const int colK = ((lane & 16) ? 8 : 0);
    int orow = m0 + (lane >> 2);
    int ncol = (lane & 3) * 2;

    float acc[8][4];
    #pragma unroll
    for (int nf = 0; nf < 8; nf++)
        #pragma unroll
        for (int e = 0; e < 4; e++) acc[nf][e] = 0.f;

    #pragma unroll
    for (int kb = 0; kb < 8; kb++) {
        uint32_t aw[4];
        ldsm_x4(aw, &Wb[(m0 + rowK) * LDWB + kb * 16 + colK]);
        #pragma unroll
        for (int nb = 0; nb < 4; nb++) {
            uint32_t bf[4];
            ldsm_x4t(bf, &In[(kb * 16 + rowK) * LDIB + nb * 16 + colK]);
            mma16816(acc[2 * nb],     aw, bf);
            mma16816(acc[2 * nb + 1], aw, bf + 2);
        }
    }

    float sc = (z == 0) ? QSCALE : 1.0f;
    float bv0 = bias[orow], bv1 = bias[orow + 8];
    size_t ob0 = ((size_t)b * CC + orow) * NS + n0;
    size_t ob1 = ob0 + (size_t)8 * NS;
    #pragma unroll
    for (int nf = 0; nf < 8; nf++) {
        int n = nf * 8 + ncol;
        *(uint32_t*)&out[ob0 + n] =
            pack_bf16((acc[nf][0] + bv0) * sc, (acc[nf][1] + bv0) * sc);
        *(uint32_t*)&out[ob1 + n] =
            pack_bf16((acc[nf][2] + bv1) * sc, (acc[nf][3] + bv1) * sc);
    }
}

// ---------------- flash attention (bf16 mma, split-KV) ------------------------
// CHAMPION SCHEDULE (rounds 6/11/13): grid (NS/64, BB, SPLIT), 128 threads.
// Q + double-K + single-V smem (72 KB) -> 3 CTAs/SM. K prefetch at loop top,
// V prefetch after AV (late-V).
#define LDB 72
#define SM_TILE (128 * LDB)

__global__ void __launch_bounds__(128, 3) attn_kernel()
{
    extern __shared__ __nv_bfloat16 sh[];
    __nv_bfloat16* Qs = sh;                                   // [128][LDB]
    __nv_bfloat16* Ksb[2] = { sh + SM_TILE, sh + 2 * SM_TILE };
    __nv_bfloat16* Vs = sh + 3 * SM_TILE;                     // single buffer

    int b  = blockIdx.y;
    int sp = blockIdx.z;
    int i0 = blockIdx.x * 64;
    int tid = threadIdx.x, lane = tid & 31, warp = tid >> 5;
    int t = lane & 3;
    int m0 = warp * 16;

    const __nv_bfloat16* gq = g_qh + (size_t)b * CC * NS + i0;
    const __nv_bfloat16* gk = g_kh + (size_t)b * CC * NS + sp * JSPAN;
    const __nv_bfloat16* gv = g_vh + (size_t)b * CC * NS + sp * JSPAN;

    // prologue: Q, K0, V0
    for (int idx = tid; idx < 1024; idx += 128) {
        int c = idx >> 3, j8 = (idx & 7) * 8;
        cp16(&Qs[c * LDB + j8], gq + (size_t)c * NS + j8);
        cp16(&Ksb[0][c * LDB + j8], gk + (size_t)c * NS + j8);
        cp16(&Vs[c * LDB + j8], gv + (size_t)c * NS + j8);
    }
    asm volatile("cp.async.commit_group;");
    asm volatile("cp.async.wait_group 0;");
    __syncthreads();

    const int rowA = (lane & 7) + ((lane & 16) ? 8 : 0);
    const int colA = ((lane & 8) ? 8 : 0);
    const int rowK = (lane & 7) + ((lane & 8) ? 8 : 0);
    const int colK = ((lane & 16) ? 8 : 0);

    uint32_t qa[8][4];
    #pragma unroll
    for (int kb = 0; kb < 8; kb++)
        ldsm_x4t(qa[kb], &Qs[(kb * 16 + rowA) * LDB + m0 + colA]);

    float mr0 = -1e30f, mr1 = -1e30f, lr0 = 0.f, lr1 = 0.f;
    float of[16][4];
    #pragma unroll
    for (int nt = 0; nt < 16; nt++)
        #pragma unroll
        for (int e = 0; e < 4; e++) of[nt][e] = 0.f;

    const int NT = JSPAN / 64;
    for (int jt = 0; jt < NT; jt++) {
        asm volatile("cp.async.wait_group 1;");
        __syncthreads();

        if (jt + 1 < NT) {
            int j0n = (jt + 1) * 64;
            __nv_bfloat16* kd = Ksb[(jt + 1) & 1];
            for (int idx = tid; idx < 1024; idx += 128) {
                int c = idx >> 3, j8 = (idx & 7) * 8;
                cp16(&kd[c * LDB + j8], gk + (size_t)c * NS + j0n + j8);
            }
        }
        asm volatile("cp.async.commit_group;");

        const __nv_bfloat16* Ks = Ksb[jt & 1];

        float sf[8][4];
        #pragma unroll
        for (int nb = 0; nb < 8; nb++)
            #pragma unroll
            for (int e = 0; e < 4; e++) sf[nb][e] = 0.f;

        #pragma unroll
        for (int kb = 0; kb < 8; kb++) {
            #pragma unroll
            for (int nbp = 0; nbp < 4; nbp++) {
                uint32_t kf[4];
                ldsm_x4t(kf, &Ks[(kb * 16 + rowK) * LDB + nbp * 16 + colK]);
                mma16816(sf[2 * nbp],     qa[kb], kf);
                mma16816(sf[2 * nbp + 1], qa[kb], kf + 2);
            }
        }

        float mx0 = -1e30f, mx1 = -1e30f;
        #pragma unroll
        for (int nb = 0; nb < 8; nb++) {
            mx0 = fmaxf(mx0, fmaxf(sf[nb][0], sf[nb][1]));
            mx1 = fmaxf(mx1, fmaxf(sf[nb][2], sf[nb][3]));
        }
        mx0 = fmaxf(mx0, __shfl_xor_sync(0xffffffffu, mx0, 1));
        mx0 = fmaxf(mx0, __shfl_xor_sync(0xffffffffu, mx0, 2));
        mx1 = fmaxf(mx1, __shfl_xor_sync(0xffffffffu, mx1, 1));
        mx1 = fmaxf(mx1, __shfl_xor_sync(0xffffffffu, mx1, 2));

        float mn0 = fmaxf(mr0, mx0), mn1 = fmaxf(mr1, mx1);
        float cr0 = ex2(mr0 - mn0),  cr1 = ex2(mr1 - mn1);
        float rs0 = 0.f, rs1 = 0.f;
        #pragma unroll
        for (int nb = 0; nb < 8; nb++) {
            sf[nb][0] = ex2(sf[nb][0] - mn0);
            sf[nb][1] = ex2(sf[nb][1] - mn0);
            sf[nb][2] = ex2(sf[nb][2] - mn1);
            sf[nb][3] = ex2(sf[nb][3] - mn1);
            rs0 += sf[nb][0] + sf[nb][1];
            rs1 += sf[nb][2] + sf[nb][3];
        }
        rs0 += __shfl_xor_sync(0xffffffffu, rs0, 1);
        rs0 += __shfl_xor_sync(0xffffffffu, rs0, 2);
        rs1 += __shfl_xor_sync(0xffffffffu, rs1, 1);
        rs1 += __shfl_xor_sync(0xffffffffu, rs1, 2);
        lr0 = lr0 * cr0 + rs0;
        lr1 = lr1 * cr1 + rs1;
        mr0 = mn0; mr1 = mn1;

        #pragma unroll
        for (int nt = 0; nt < 16; nt++) {
            of[nt][0] *= cr0; of[nt][1] *= cr0;
            of[nt][2] *= cr1; of[nt][3] *= cr1;
        }

        uint32_t pa[4][4];
        #pragma unroll
        for (int kt = 0; kt < 4; kt++) {
            pa[kt][0] = pack_bf16(sf[2 * kt][0],     sf[2 * kt][1]);
            pa[kt][1] = pack_bf16(sf[2 * kt][2],     sf[2 * kt][3]);
            pa[kt][2] = pack_bf16(sf[2 * kt + 1][0], sf[2 * kt + 1][1]);
            pa[kt][3] = pack_bf16(sf[2 * kt + 1][2], sf[2 * kt + 1][3]);
        }

        asm volatile("cp.async.wait_group 1;");
        __syncthreads();

        #pragma unroll
        for (int ntp = 0; ntp < 8; ntp++) {
            #pragma unroll
            for (int kt = 0; kt < 4; kt++) {
                uint32_t vf[4];
                ldsm_x4(vf, &Vs[(ntp * 16 + rowA) * LDB + kt * 16 + colA]);
                mma16816(of[2 * ntp],     pa[kt], vf);
                mma16816(of[2 * ntp + 1], pa[kt], vf + 2);
            }
        }
        __syncthreads();

        if (jt + 1 < NT) {
            int j0n = (jt + 1) * 64;
            for (int idx = tid; idx < 1024; idx += 128) {
                int c = idx >> 3, j8 = (idx & 7) * 8;
                cp16(&Vs[c * LDB + j8], gv + (size_t)c * NS + j0n + j8);
            }
        }
        asm volatile("cp.async.commit_group;");
    }
    asm volatile("cp.async.wait_group 0;");

    // epilogue: per-split-normalized bf16 partials, [n][c] layout
    float inv0 = 1.0f / lr0, inv1 = 1.0f / lr1;
    int ig = i0 + m0 + (lane >> 2);
    __nv_bfloat16* po = g_pob + ((size_t)(sp * BB + b)) * NS * CC;
    #pragma unroll
    for (int nt = 0; nt < 16; nt++) {
        int c = 8 * nt + 2 * t;
        *(uint32_t*)&po[(size_t)ig * CC + c] =
            pack_bf16(of[nt][0] * inv0, of[nt][1] * inv0);
        *(uint32_t*)&po[(size_t)(ig + 8) * CC + c] =
            pack_bf16(of[nt][2] * inv1, of[nt][3] * inv1);
    }
    if (t == 0) {
        size_t mb = (size_t)(sp * BB + b) * NS;
        g_pm[mb + ig]     = mr0;
        g_pm[mb + ig + 8] = mr1;
        g_pl[mb + ig]     = lr0;
        g_pl[mb + ig + 8] = lr1;
    }
}

// ---------------- fused split-combine + output projection (bf16 mma) ----------
// grid (NS/32, BB, 2): 32-token tiles, 512 CTAs (champion round-13 form).
#define LDC 136
__global__ void __launch_bounds__(128) proj_out_kernel(
    const float* __restrict__ bias,
    const float* __restrict__ xres, float* __restrict__ out)
{
    extern __shared__ char smraw[];
    __nv_bfloat16* Wb = (__nv_bfloat16*)smraw;        // [64][LDC]
    __nv_bfloat16* P0 = Wb + 64 * LDC;                // [32 n][LDC c]
    __nv_bfloat16* P1 = P0 + 32 * LDC;                // [32 n][LDC c]
    __nv_bfloat16* In = P1 + 32 * LDC;                // [32 n][LDC c]
    float* A0 = (float*)(In + 32 * LDC);              // [32]
    float* A1 = A0 + 32;

    int b  = blockIdx.y;
    int mh = blockIdx.z;
    int n0 = blockIdx.x * 32;
    int tid = threadIdx.x;

    const __nv_bfloat16* wsrc = g_wb + 3 * CC * CC + (size_t)(mh * 64) * CC;
    const __nv_bfloat16* po0 = g_pob + (size_t)b * NS * CC + (size_t)n0 * CC;
    const __nv_bfloat16* po1 = g_pob + (size_t)(BB + b) * NS * CC + (size_t)n0 * CC;

    for (int idx = tid; idx < 512; idx += 128) {
        int r = idx >> 4, ch = (idx & 15) * 8;
        cp16(&P0[r * LDC + ch], po0 + r * CC + ch);
        cp16(&P1[r * LDC + ch], po1 + r * CC + ch);
    }
    for (int idx = tid; idx < 1024; idx += 128) {
        int r = idx >> 4, ch = (idx & 15) * 8;
        cp16(&Wb[r * LDC + ch], wsrc + r * CC + ch);
    }
    asm volatile("cp.async.commit_group;");

    if (tid < 32) {
        int i = n0 + tid;
        float m0v = g_pm[(size_t)b * NS + i];
        float m1v = g_pm[(size_t)(BB + b) * NS + i];
        float l0v = g_pl[(size_t)b * NS + i];
        float l1v = g_pl[(size_t)(BB + b) * NS + i];
        float mm = fmaxf(m0v, m1v);
        float e0 = l0v * ex2(m0v - mm), e1 = l1v * ex2(m1v - mm);
        float inv = 1.0f / (e0 + e1);
        A0[tid] = e0 * inv;
        A1[tid] = e1 * inv;
    }
    asm volatile("cp.async.wait_group 0;");
    __syncthreads();

    for (int idx = tid; idx < 32 * 64; idx += 128) {
        int n = idx >> 6, cp = idx & 63;
        uint32_t u0 = ((const uint32_t*)&P0[n * LDC])[cp];
        uint32_t u1 = ((const uint32_t*)&P1[n * LDC])[cp];
        __nv_bfloat162 h0 = *(__nv_bfloat162*)&u0;
        __nv_bfloat162 h1 = *(__nv_bfloat162*)&u1;
        float a0 = A0[n], a1 = A1[n];
        float rx = a0 * __bfloat162float(h0.x) + a1 * __bfloat162float(h1.x);
        float ry = a0 * __bfloat162float(h0.y) + a1 * __bfloat162float(h1.y);
        ((uint32_t*)&In[n * LDC])[cp] = pack_bf16(rx, ry);
    }
    __syncthreads();

    int lane = tid & 31, warp = tid >> 5;
    int m0 = warp * 16;
    const int rowA = (lane & 7) + ((lane & 16) ? 8 : 0);
    const int colA = ((lane & 8) ? 8 : 0);
    const int rowK = (lane & 7) + ((lane & 8) ? 8 : 0);
    const int colK = ((lane & 16) ? 8 : 0);

    float acc[4][4];
    #pragma unroll
    for (int nf = 0; nf < 4; nf++)
        #pragma unroll
        for (int e = 0; e < 4; e++) acc[nf][e] = 0.f;

    #pragma unroll
    for (int kb = 0; kb < 8; kb++) {
        uint32_t aw[4];
        ldsm_x4(aw, &Wb[(m0 + rowK) * LDC + kb * 16 + colK]);
        #pragma unroll
        for (int nb = 0; nb < 2; nb++) {
            uint32_t vf[4];
            ldsm_x4(vf, &In[(nb * 16 + rowA) * LDC + kb * 16 + colA]);
            mma16816(acc[2 * nb],     aw, vf);
            mma16816(acc[2 * nb + 1], aw, vf + 2);
        }
    }

    int orow = mh * 64 + m0 + (lane >> 2);
    int ncol = (lane & 3) * 2;
    float bv0 = bias[orow], bv1 = bias[orow + 8];
    size_t ob0 = ((size_t)b * CC + orow) * NS + n0;
    size_t ob1 = ob0 + (size_t)8 * NS;
    #pragma unroll
    for (int nf = 0; nf < 4; nf++) {
        int n = nf * 8 + ncol;
        float2 x0 = *(const float2*)&xres[ob0 + n];
        float2 x1 = *(const float2*)&xres[ob1 + n];
        float2 r0 = { acc[nf][0] + bv0 + x0.x, acc[nf][1] + bv0 + x0.y };
        float2 r1 = { acc[nf][2] + bv1 + x1.x, acc[nf][3] + bv1 + x1.y };
        *(float2*)&out[ob0 + n] = r0;
        *(float2*)&out[ob1 + n] = r1;
    }
}

// ---------------- launcher ---------------------------------------------------
extern "C" void kernel_launch(void* const* d_in, const int* in_sizes, int n_in,
                              void* d_out, int out_size)
{
    const float* x  = (const float*)d_in[0];
    const float* c  = (const float*)d_in[1];
    const float* g1 = (const float*)d_in[2];
    const float* b1 = (const float*)d_in[3];
    const float* g2 = (const float*)d_in[4];
    const float* b2 = (const float*)d_in[5];
    const float* wq = (const float*)d_in[6];
    const float* bq = (const float*)d_in[7];
    const float* wk = (const float*)d_in[8];
    const float* bk = (const float*)d_in[9];
    const float* wv = (const float*)d_in[10];
    const float* bv = (const float*)d_in[11];
    const float* wp = (const float*)d_in[12];
    const float* bp = (const float*)d_in[13];
    float* out = (float*)d_out;

    const int QKV_SMEM  = (CC * LDWB + CC * LDIB) * 2 + CC * LDRF * 4 + 2 * CC * 4;  // 89088
    const int PROJ_SMEM = (64 + 3 * 32) * LDC * 2 + 2 * 32 * 4;                      // 43776
    const int ATTN_SMEM = 4 * SM_TILE * 2;                                           // 73728
    cudaFuncSetAttribute(qkv_kernel,      cudaFuncAttributeMaxDynamicSharedMemorySize, QKV_SMEM);
    cudaFuncSetAttribute(proj_out_kernel, cudaFuncAttributeMaxDynamicSharedMemorySize, PROJ_SMEM);
    cudaFuncSetAttribute(attn_kernel,     cudaFuncAttributeMaxDynamicSharedMemorySize, ATTN_SMEM);

    prep_kernel<<<320, 256>>>(x, c, wq, wk, wv, wp);

    dim3 gq(NS / 64, BB, 3);
    qkv_kernel<<<gq, 256, QKV_SMEM>>>(bq, bk, bv, g1, b1, g2, b2, x, c);

    dim3 ga(NS / 64, BB, SPLIT);
    attn_kernel<<<ga, 128, ATTN_SMEM>>>();

    dim3 gp(NS / 32, BB, 2);
    proj_out_kernel<<<gp, 128, PROJ_SMEM>>>(bp, x, out);
}